// round 1
// baseline (speedup 1.0000x reference)
#include <cuda_runtime.h>
#include <cstdint>
#include <cstdio>

#define DIMB   25
#define NNODES 20000
#define NFEAT  300
#define NHID   64
#define NCLASS 50
#define NC2    52            // NCLASS padded to multiple of 4 (16B rows)
#define HCAT   (DIMB * NHID) // 1600

// ---------------- scratch (static device memory; no allocs allowed) ----------
__device__ float g_sup1[(size_t)DIMB * NNODES * NHID];   // 128 MB
__device__ float g_h1cat[(size_t)NNODES * HCAT];         // 128 MB
__device__ float g_sup2[(size_t)DIMB * NNODES * NC2];    // 104 MB
__device__ float g_acc2[(size_t)DIMB * NNODES * NC2];    // 104 MB

// ---------------- vectorized global reduction (sm_90+) -----------------------
__device__ __forceinline__ void red_add_v4(float* addr, float4 v) {
    asm volatile("red.global.add.v4.f32 [%0], {%1,%2,%3,%4};"
                 :: "l"(addr), "f"(v.x), "f"(v.y), "f"(v.z), "f"(v.w)
                 : "memory");
}

// ---------------- zero scratch that is scatter-accumulated -------------------
__global__ void zero_kernel(float* __restrict__ h1cat, float* __restrict__ acc2) {
    size_t i  = (size_t)blockIdx.x * blockDim.x + threadIdx.x;
    const size_t n1 = (size_t)NNODES * HCAT / 4;
    const size_t n2 = (size_t)DIMB * NNODES * NC2 / 4;
    float4 z = make_float4(0.f, 0.f, 0.f, 0.f);
    if (i < n1)            ((float4*)h1cat)[i]      = z;
    else if (i < n1 + n2)  ((float4*)acc2)[i - n1]  = z;
}

// ---------------- batched fp32 GEMM: C[d] = A (N x K) * B[d] (K x NCB) -------
// BM=128, BN=64, BK=8, 256 threads, 8x4 microtile per thread.
// blockIdx.x = branch d (fastest-varying -> branches sharing a row tile of A
// run concurrently and share it through L2); blockIdx.y = row tile.
template <int K, int NCB, int NCC>
__global__ void __launch_bounds__(256)
gemm_kernel(const float* __restrict__ A, const float* __restrict__ B,
            float* __restrict__ C) {
    constexpr int BM = 128, BN = 64, BK = 8;
    __shared__ float As[BK][BM + 4];   // padded: conflict-free transpose store
    __shared__ float Bs[BK][BN];

    const int d  = blockIdx.x;
    const int n0 = blockIdx.y * BM;
    const float* Bd = B + (size_t)d * K * NCB;
    float*       Cd = C + (size_t)d * NNODES * NCC;

    const int tid   = threadIdx.x;
    const int tx    = tid & 15;        // 16 cols of threads
    const int ty    = tid >> 4;        // 16 rows of threads
    const int rbase = ty * 8;
    const int cbase = tx * 4;

    float acc[8][4] = {};

    #pragma unroll 1
    for (int k0 = 0; k0 < K; k0 += BK) {
        // load A tile (BM x BK), transposed into As[k][r]
        #pragma unroll
        for (int j = 0; j < 4; j++) {
            int idx = tid + j * 256;           // 0..1023
            int r = idx >> 3, c = idx & 7;
            int gr = n0 + r, gc = k0 + c;
            float v = 0.f;
            if (gr < NNODES && gc < K) v = A[(size_t)gr * K + gc];
            As[c][r] = v;
        }
        // load B tile (BK x BN), zero-fill beyond NCB
        #pragma unroll
        for (int j = 0; j < 2; j++) {
            int idx = tid + j * 256;           // 0..511
            int r = idx >> 6, c = idx & 63;
            int gk = k0 + r;
            float v = 0.f;
            if (gk < K && c < NCB) v = Bd[(size_t)gk * NCB + c];
            Bs[r][c] = v;
        }
        __syncthreads();

        #pragma unroll
        for (int k = 0; k < BK; k++) {
            float4 a0 = *(const float4*)&As[k][rbase];
            float4 a1 = *(const float4*)&As[k][rbase + 4];
            float4 bv = *(const float4*)&Bs[k][cbase];
            float a[8] = {a0.x, a0.y, a0.z, a0.w, a1.x, a1.y, a1.z, a1.w};
            float b[4] = {bv.x, bv.y, bv.z, bv.w};
            #pragma unroll
            for (int i = 0; i < 8; i++)
                #pragma unroll
                for (int j = 0; j < 4; j++)
                    acc[i][j] += a[i] * b[j];
        }
        __syncthreads();
    }

    #pragma unroll
    for (int i = 0; i < 8; i++) {
        int gr = n0 + rbase + i;
        if (gr >= NNODES) continue;
        #pragma unroll
        for (int j = 0; j < 4; j++) {
            int gc = cbase + j;
            if (gc < NCC) Cd[(size_t)gr * NCC + gc] = acc[i][j];
        }
    }
}

// ---------------- SpMM layer 1: scatter into permuted h1cat ------------------
// 16 threads per edge, each covers one float4 of the 64-float payload.
// Writes land at h1cat[row][d*64 + 4*lane .. +3]  (the transpose is free).
__global__ void spmm1_kernel(const int* __restrict__ rows,
                             const int* __restrict__ cols,
                             const float* __restrict__ vals, int E,
                             const float* __restrict__ sup1,
                             float* __restrict__ h1cat) {
    const int d = blockIdx.y;
    long t = (long)blockIdx.x * blockDim.x + threadIdx.x;
    int e = (int)(t >> 4);
    int lane = (int)(t & 15);
    if (e >= E) return;
    size_t eo = (size_t)d * E + e;
    int r = rows[eo];
    int c = cols[eo];
    float v = vals[eo];
    float4 s = *(const float4*)(sup1 + ((size_t)d * NNODES + c) * NHID + lane * 4);
    float4 p = make_float4(v * s.x, v * s.y, v * s.z, v * s.w);
    red_add_v4(h1cat + (size_t)r * HCAT + d * NHID + lane * 4, p);
}

// ---------------- bias + relu on h1cat (b1 layout [d][64] == row layout) -----
__global__ void bias_relu_kernel(const float* __restrict__ b1,
                                 float* __restrict__ h1cat) {
    size_t i = (size_t)blockIdx.x * blockDim.x + threadIdx.x;
    if (i >= (size_t)NNODES * HCAT / 4) return;
    float4 h = ((float4*)h1cat)[i];
    int k = (int)(i % (HCAT / 4));
    float4 b = ((const float4*)b1)[k];
    h.x = fmaxf(h.x + b.x, 0.f);
    h.y = fmaxf(h.y + b.y, 0.f);
    h.z = fmaxf(h.z + b.z, 0.f);
    h.w = fmaxf(h.w + b.w, 0.f);
    ((float4*)h1cat)[i] = h;
}

// ---------------- SpMM layer 2: 52-float padded payload = 13 float4 ----------
__global__ void spmm2_kernel(const int* __restrict__ rows,
                             const int* __restrict__ cols,
                             const float* __restrict__ vals, int E,
                             const float* __restrict__ sup2,
                             float* __restrict__ acc2) {
    const int d = blockIdx.y;
    long t = (long)blockIdx.x * blockDim.x + threadIdx.x;
    int e = (int)(t >> 4);
    int lane = (int)(t & 15);
    if (e >= E || lane >= NC2 / 4) return;   // 13 active lanes of 16
    size_t eo = (size_t)d * E + e;
    int r = rows[eo];
    int c = cols[eo];
    float v = vals[eo];
    float4 s = *(const float4*)(sup2 + ((size_t)d * NNODES + c) * NC2 + lane * 4);
    float4 p = make_float4(v * s.x, v * s.y, v * s.z, v * s.w);
    red_add_v4(acc2 + ((size_t)d * NNODES + r) * NC2 + lane * 4, p);
}

// ---------------- bias + relu + max-pool over branches -----------------------
// relu(x) then max over d  ==  max(0, max_d(x))
__global__ void final_kernel(const float* __restrict__ b2,
                             const float* __restrict__ acc2,
                             float* __restrict__ out) {
    int i = blockIdx.x * blockDim.x + threadIdx.x;
    if (i >= NNODES * NCLASS) return;
    int n = i / NCLASS, c = i % NCLASS;
    float m = 0.f;
    #pragma unroll
    for (int d = 0; d < DIMB; d++)
        m = fmaxf(m, acc2[((size_t)d * NNODES + n) * NC2 + c] + b2[d * NCLASS + c]);
    out[i] = m;
}

// ---------------- launch ----------------------------------------------------
extern "C" void kernel_launch(void* const* d_in, const int* in_sizes, int n_in,
                              void* d_out, int out_size) {
    const float* x        = (const float*)d_in[0];
    const int*   adj_rows = (const int*)d_in[1];
    const int*   adj_cols = (const int*)d_in[2];
    const float* adj_vals = (const float*)d_in[3];
    const float* W1       = (const float*)d_in[4];
    const float* b1       = (const float*)d_in[5];
    const float* W2       = (const float*)d_in[6];
    const float* b2       = (const float*)d_in[7];
    float*       out      = (float*)d_out;

    const int E = in_sizes[1] / DIMB;

    float *p_sup1, *p_h1cat, *p_sup2, *p_acc2;
    cudaGetSymbolAddress((void**)&p_sup1,  g_sup1);
    cudaGetSymbolAddress((void**)&p_h1cat, g_h1cat);
    cudaGetSymbolAddress((void**)&p_sup2,  g_sup2);
    cudaGetSymbolAddress((void**)&p_acc2,  g_acc2);

    // 1. zero the scatter accumulators
    {
        size_t zn = ((size_t)NNODES * HCAT + (size_t)DIMB * NNODES * NC2) / 4;
        zero_kernel<<<(unsigned)((zn + 255) / 256), 256>>>(p_h1cat, p_acc2);
    }

    const int rowTiles = (NNODES + 127) / 128;

    // 2. sup1[d] = x * W1[d]
    gemm_kernel<NFEAT, NHID, NHID>
        <<<dim3(DIMB, rowTiles), 256>>>(x, W1, p_sup1);

    // 3. spmm layer 1 (scatter directly into permuted h1cat)
    {
        long threads = (long)E * 16;
        dim3 grid((unsigned)((threads + 255) / 256), DIMB);
        spmm1_kernel<<<grid, 256>>>(adj_rows, adj_cols, adj_vals, E, p_sup1, p_h1cat);
    }

    // 4. bias + relu
    {
        size_t n = (size_t)NNODES * HCAT / 4;
        bias_relu_kernel<<<(unsigned)((n + 255) / 256), 256>>>(b1, p_h1cat);
    }

    // 5. sup2[d] = h1cat * W2[d]   (NCLASS padded to 52 in C)
    gemm_kernel<HCAT, NCLASS, NC2>
        <<<dim3(DIMB, rowTiles), 256>>>(p_h1cat, W2, p_sup2);

    // 6. spmm layer 2
    {
        long threads = (long)E * 16;
        dim3 grid((unsigned)((threads + 255) / 256), DIMB);
        spmm2_kernel<<<grid, 256>>>(adj_rows, adj_cols, adj_vals, E, p_sup2, p_acc2);
    }

    // 7. bias + relu + max over branches
    final_kernel<<<(NNODES * NCLASS + 255) / 256, 256>>>(b2, p_acc2, out);
}

// round 2
// speedup vs baseline: 1.2402x; 1.2402x over previous
#include <cuda_runtime.h>
#include <cstdint>
#include <cstdio>

#define DIMB   25
#define NNODES 20000
#define NFEAT  300
#define NHID   64
#define NCLASS 50
#define NC2    52            // NCLASS padded to multiple of 4 (16B rows)
#define HCAT   (DIMB * NHID) // 1600

// ---------------- scratch (static device memory; no allocs allowed) ----------
__device__ float g_sup1[(size_t)DIMB * NNODES * NHID];   // 128 MB
__device__ float g_h1cat[(size_t)NNODES * HCAT];         // 128 MB
__device__ float g_sup2[(size_t)DIMB * NNODES * NC2];    // 104 MB
__device__ float g_acc2[(size_t)DIMB * NNODES * NC2];    // 104 MB

// ---------------- helpers ----------------------------------------------------
__device__ __forceinline__ void red_add_v4(float* addr, float4 v) {
    asm volatile("red.global.add.v4.f32 [%0], {%1,%2,%3,%4};"
                 :: "l"(addr), "f"(v.x), "f"(v.y), "f"(v.z), "f"(v.w)
                 : "memory");
}

__device__ __forceinline__ float cvt_tf32(float f) {
    uint32_t o;
    asm("cvt.rna.tf32.f32 %0, %1;" : "=r"(o) : "f"(f));
    return __uint_as_float(o);
}

__device__ __forceinline__ void mma_tf32(float& c0, float& c1, float& c2, float& c3,
                                         uint32_t a0, uint32_t a1, uint32_t a2, uint32_t a3,
                                         uint32_t b0, uint32_t b1) {
    asm volatile("mma.sync.aligned.m16n8k8.row.col.f32.tf32.tf32.f32 "
                 "{%0,%1,%2,%3}, {%4,%5,%6,%7}, {%8,%9}, {%0,%1,%2,%3};"
                 : "+f"(c0), "+f"(c1), "+f"(c2), "+f"(c3)
                 : "r"(a0), "r"(a1), "r"(a2), "r"(a3), "r"(b0), "r"(b1));
}

// ---------------- zero scratch that is scatter-accumulated -------------------
__global__ void zero_kernel(float* __restrict__ h1cat, float* __restrict__ acc2) {
    size_t i  = (size_t)blockIdx.x * blockDim.x + threadIdx.x;
    const size_t n1 = (size_t)NNODES * HCAT / 4;
    const size_t n2 = (size_t)DIMB * NNODES * NC2 / 4;
    float4 z = make_float4(0.f, 0.f, 0.f, 0.f);
    if (i < n1)            ((float4*)h1cat)[i]      = z;
    else if (i < n1 + n2)  ((float4*)acc2)[i - n1]  = z;
}

// ---------------- batched tf32 tensor-core GEMM ------------------------------
// C[d] (NNODES x NCC) = A (NNODES x K) * B[d] (K x NCB), zero-padded to BN=64.
// BM=128, BN=64, BK=32, 256 threads = 8 warps (4x2), warp tile 32x32.
// mma.sync m16n8k8 tf32. Single-buffered SMEM with register prefetch of the
// next K-tile so global latency overlaps compute.
template <int K, int NCB, int NCC>
__global__ void __launch_bounds__(256)
mma_gemm_kernel(const float* __restrict__ A, const float* __restrict__ B,
                float* __restrict__ C) {
    constexpr int BM = 128, BN = 64, BK = 32;
    __shared__ float As[BM][36];   // stride 36: (g*4+tig) unique banks
    __shared__ float Bs[BK][68];   // stride 68: (tig*4+g) unique banks

    const int d  = blockIdx.x;
    const int n0 = blockIdx.y * BM;
    const float* Bd = B + (size_t)d * K * NCB;
    float*       Cd = C + (size_t)d * NNODES * NCC;

    const int tid  = threadIdx.x;
    const int w    = tid >> 5;
    const int lane = tid & 31;
    const int g    = lane >> 2;
    const int tig  = lane & 3;
    const int wm   = (w & 3) * 32;
    const int wn   = (w >> 2) * 32;

    float acc[2][4][4];
    #pragma unroll
    for (int mt = 0; mt < 2; mt++)
        #pragma unroll
        for (int nt = 0; nt < 4; nt++)
            #pragma unroll
            for (int i = 0; i < 4; i++) acc[mt][nt][i] = 0.f;

    float aReg[16];
    float bReg[8];

    // --- staging load: next A tile (BM x BK) into regs -----------------------
    auto loadA = [&](int k0) {
        #pragma unroll
        for (int j = 0; j < 4; j++) {
            int linear = tid + j * 256;        // 0..1023
            int r  = linear >> 3;
            int c  = (linear & 7) * 4;
            int gr = n0 + r, gc = k0 + c;
            if (gr < NNODES && gc + 3 < K) {
                float4 v = *(const float4*)(A + (size_t)gr * K + gc);
                aReg[j*4+0] = v.x; aReg[j*4+1] = v.y;
                aReg[j*4+2] = v.z; aReg[j*4+3] = v.w;
            } else {
                #pragma unroll
                for (int i = 0; i < 4; i++)
                    aReg[j*4+i] = (gr < NNODES && gc + i < K)
                                  ? A[(size_t)gr * K + gc + i] : 0.f;
            }
        }
    };
    auto storeA = [&]() {
        #pragma unroll
        for (int j = 0; j < 4; j++) {
            int linear = tid + j * 256;
            int r = linear >> 3;
            int c = (linear & 7) * 4;
            #pragma unroll
            for (int i = 0; i < 4; i++) As[r][c + i] = cvt_tf32(aReg[j*4+i]);
        }
    };
    // --- staging load: next B tile (BK x BN) -------------------------------
    auto loadB = [&](int k0) {
        #pragma unroll
        for (int j = 0; j < 8; j++) {
            int linear = tid + j * 256;        // 0..2047
            int r = linear >> 6;
            int c = linear & 63;
            int gk = k0 + r;
            bReg[j] = (c < NCB && gk < K) ? Bd[(size_t)gk * NCB + c] : 0.f;
        }
    };
    auto storeB = [&]() {
        #pragma unroll
        for (int j = 0; j < 8; j++) {
            int linear = tid + j * 256;
            int r = linear >> 6;
            int c = linear & 63;
            Bs[r][c] = cvt_tf32(bReg[j]);
        }
    };

    loadA(0); loadB(0);

    for (int k0 = 0; k0 < K; k0 += BK) {
        storeA(); storeB();
        __syncthreads();
        if (k0 + BK < K) { loadA(k0 + BK); loadB(k0 + BK); }

        #pragma unroll
        for (int ks = 0; ks < 4; ks++) {
            int k = ks * 8;
            uint32_t a[2][4];
            #pragma unroll
            for (int mt = 0; mt < 2; mt++) {
                int m = wm + mt * 16;
                a[mt][0] = __float_as_uint(As[m + g    ][k + tig    ]);
                a[mt][1] = __float_as_uint(As[m + g + 8][k + tig    ]);
                a[mt][2] = __float_as_uint(As[m + g    ][k + tig + 4]);
                a[mt][3] = __float_as_uint(As[m + g + 8][k + tig + 4]);
            }
            uint32_t b[4][2];
            #pragma unroll
            for (int nt = 0; nt < 4; nt++) {
                int n = wn + nt * 8;
                b[nt][0] = __float_as_uint(Bs[k + tig    ][n + g]);
                b[nt][1] = __float_as_uint(Bs[k + tig + 4][n + g]);
            }
            #pragma unroll
            for (int mt = 0; mt < 2; mt++)
                #pragma unroll
                for (int nt = 0; nt < 4; nt++)
                    mma_tf32(acc[mt][nt][0], acc[mt][nt][1],
                             acc[mt][nt][2], acc[mt][nt][3],
                             a[mt][0], a[mt][1], a[mt][2], a[mt][3],
                             b[nt][0], b[nt][1]);
        }
        __syncthreads();
    }

    // --- epilogue: c0,c1 -> (g, 2*tig..+1), c2,c3 -> (g+8, ...) --------------
    #pragma unroll
    for (int mt = 0; mt < 2; mt++) {
        int gr0 = n0 + wm + mt * 16 + g;
        #pragma unroll
        for (int nt = 0; nt < 4; nt++) {
            int gc = wn + nt * 8 + tig * 2;
            if (gc >= NCC) continue;
            if (gr0 < NNODES)
                *(float2*)(Cd + (size_t)gr0 * NCC + gc) =
                    make_float2(acc[mt][nt][0], acc[mt][nt][1]);
            if (gr0 + 8 < NNODES)
                *(float2*)(Cd + (size_t)(gr0 + 8) * NCC + gc) =
                    make_float2(acc[mt][nt][2], acc[mt][nt][3]);
        }
    }
}

// ---------------- SpMM layer 1: scatter into permuted h1cat ------------------
// 16 threads per edge, each covers one float4 of the 64-float payload.
__global__ void spmm1_kernel(const int* __restrict__ rows,
                             const int* __restrict__ cols,
                             const float* __restrict__ vals, int E,
                             const float* __restrict__ sup1,
                             float* __restrict__ h1cat) {
    const int d = blockIdx.y;
    long t = (long)blockIdx.x * blockDim.x + threadIdx.x;
    int e = (int)(t >> 4);
    int lane = (int)(t & 15);
    if (e >= E) return;
    size_t eo = (size_t)d * E + e;
    int r = rows[eo];
    int c = cols[eo];
    float v = vals[eo];
    float4 s = *(const float4*)(sup1 + ((size_t)d * NNODES + c) * NHID + lane * 4);
    float4 p = make_float4(v * s.x, v * s.y, v * s.z, v * s.w);
    red_add_v4(h1cat + (size_t)r * HCAT + d * NHID + lane * 4, p);
}

// ---------------- bias + relu on h1cat ---------------------------------------
__global__ void bias_relu_kernel(const float* __restrict__ b1,
                                 float* __restrict__ h1cat) {
    size_t i = (size_t)blockIdx.x * blockDim.x + threadIdx.x;
    if (i >= (size_t)NNODES * HCAT / 4) return;
    float4 h = ((float4*)h1cat)[i];
    int k = (int)(i % (HCAT / 4));
    float4 b = ((const float4*)b1)[k];
    h.x = fmaxf(h.x + b.x, 0.f);
    h.y = fmaxf(h.y + b.y, 0.f);
    h.z = fmaxf(h.z + b.z, 0.f);
    h.w = fmaxf(h.w + b.w, 0.f);
    ((float4*)h1cat)[i] = h;
}

// ---------------- SpMM layer 2: 13 float4 lanes per edge (exact) -------------
__global__ void spmm2_kernel(const int* __restrict__ rows,
                             const int* __restrict__ cols,
                             const float* __restrict__ vals, int E,
                             const float* __restrict__ sup2,
                             float* __restrict__ acc2) {
    const int d = blockIdx.y;
    long t = (long)blockIdx.x * blockDim.x + threadIdx.x;
    int e = (int)(t / 13);
    int lane = (int)(t - 13L * e);
    if (e >= E) return;
    size_t eo = (size_t)d * E + e;
    int r = rows[eo];
    int c = cols[eo];
    float v = vals[eo];
    float4 s = *(const float4*)(sup2 + ((size_t)d * NNODES + c) * NC2 + lane * 4);
    float4 p = make_float4(v * s.x, v * s.y, v * s.z, v * s.w);
    red_add_v4(acc2 + ((size_t)d * NNODES + r) * NC2 + lane * 4, p);
}

// ---------------- bias + relu + max-pool over branches -----------------------
__global__ void final_kernel(const float* __restrict__ b2,
                             const float* __restrict__ acc2,
                             float* __restrict__ out) {
    int i = blockIdx.x * blockDim.x + threadIdx.x;
    if (i >= NNODES * NCLASS) return;
    int n = i / NCLASS, c = i % NCLASS;
    float m = 0.f;
    #pragma unroll
    for (int d = 0; d < DIMB; d++)
        m = fmaxf(m, acc2[((size_t)d * NNODES + n) * NC2 + c] + b2[d * NCLASS + c]);
    out[i] = m;
}

// ---------------- launch ----------------------------------------------------
extern "C" void kernel_launch(void* const* d_in, const int* in_sizes, int n_in,
                              void* d_out, int out_size) {
    const float* x        = (const float*)d_in[0];
    const int*   adj_rows = (const int*)d_in[1];
    const int*   adj_cols = (const int*)d_in[2];
    const float* adj_vals = (const float*)d_in[3];
    const float* W1       = (const float*)d_in[4];
    const float* b1       = (const float*)d_in[5];
    const float* W2       = (const float*)d_in[6];
    const float* b2       = (const float*)d_in[7];
    float*       out      = (float*)d_out;

    const int E = in_sizes[1] / DIMB;

    float *p_sup1, *p_h1cat, *p_sup2, *p_acc2;
    cudaGetSymbolAddress((void**)&p_sup1,  g_sup1);
    cudaGetSymbolAddress((void**)&p_h1cat, g_h1cat);
    cudaGetSymbolAddress((void**)&p_sup2,  g_sup2);
    cudaGetSymbolAddress((void**)&p_acc2,  g_acc2);

    // 1. zero the scatter accumulators
    {
        size_t zn = ((size_t)NNODES * HCAT + (size_t)DIMB * NNODES * NC2) / 4;
        zero_kernel<<<(unsigned)((zn + 255) / 256), 256>>>(p_h1cat, p_acc2);
    }

    const int rowTiles = (NNODES + 127) / 128;

    // 2. sup1[d] = x * W1[d]   (tf32 tensor cores)
    mma_gemm_kernel<NFEAT, NHID, NHID>
        <<<dim3(DIMB, rowTiles), 256>>>(x, W1, p_sup1);

    // 3. spmm layer 1 (scatter directly into permuted h1cat)
    {
        long threads = (long)E * 16;
        dim3 grid((unsigned)((threads + 255) / 256), DIMB);
        spmm1_kernel<<<grid, 256>>>(adj_rows, adj_cols, adj_vals, E, p_sup1, p_h1cat);
    }

    // 4. bias + relu
    {
        size_t n = (size_t)NNODES * HCAT / 4;
        bias_relu_kernel<<<(unsigned)((n + 255) / 256), 256>>>(b1, p_h1cat);
    }

    // 5. sup2[d] = h1cat * W2[d]   (tf32 tensor cores, NCLASS padded to 52)
    mma_gemm_kernel<HCAT, NCLASS, NC2>
        <<<dim3(DIMB, rowTiles), 256>>>(p_h1cat, W2, p_sup2);

    // 6. spmm layer 2
    {
        long threads = (long)E * 13;
        dim3 grid((unsigned)((threads + 255) / 256), DIMB);
        spmm2_kernel<<<grid, 256>>>(adj_rows, adj_cols, adj_vals, E, p_sup2, p_acc2);
    }

    // 7. bias + relu + max over branches
    final_kernel<<<(NNODES * NCLASS + 255) / 256, 256>>>(b2, p_acc2, out);
}

// round 3
// speedup vs baseline: 1.5386x; 1.2406x over previous
#include <cuda_runtime.h>
#include <cstdint>
#include <cstdio>

#define DIMB   25
#define NNODES 20000
#define NFEAT  300
#define NHID   64
#define NCLASS 50
#define NC2    52             // NCLASS padded to 52 (16B rows)
#define HCAT   (DIMB * NHID)  // 1600
#define NW2    (DIMB * NC2)   // 1300

// ---------------- scratch (static device memory; no allocs allowed) ----------
__device__ float g_xr   [(size_t)NNODES * NFEAT];   // 24 MB  (tf32-rounded x)
__device__ float g_w1   [(size_t)NFEAT * HCAT];     // 1.9 MB (repacked W1)
__device__ float g_w2   [(size_t)HCAT * NW2];       // 8.3 MB (repacked W2)
__device__ float g_sup1 [(size_t)NNODES * HCAT];    // 128 MB
__device__ float g_h1cat[(size_t)NNODES * HCAT];    // 128 MB
__device__ float g_sup2 [(size_t)NNODES * NW2];     // 104 MB
__device__ float g_acc2 [(size_t)NNODES * NW2];     // 104 MB

// ---------------- helpers ----------------------------------------------------
__device__ __forceinline__ void red_add_v4(float* addr, float4 v) {
    asm volatile("red.global.add.v4.f32 [%0], {%1,%2,%3,%4};"
                 :: "l"(addr), "f"(v.x), "f"(v.y), "f"(v.z), "f"(v.w)
                 : "memory");
}

__device__ __forceinline__ float cvt_tf32(float f) {
    uint32_t o;
    asm("cvt.rna.tf32.f32 %0, %1;" : "=r"(o) : "f"(f));
    return __uint_as_float(o);
}

__device__ __forceinline__ void mma_tf32(float& c0, float& c1, float& c2, float& c3,
                                         uint32_t a0, uint32_t a1, uint32_t a2, uint32_t a3,
                                         uint32_t b0, uint32_t b1) {
    asm volatile("mma.sync.aligned.m16n8k8.row.col.f32.tf32.tf32.f32 "
                 "{%0,%1,%2,%3}, {%4,%5,%6,%7}, {%8,%9}, {%0,%1,%2,%3};"
                 : "+f"(c0), "+f"(c1), "+f"(c2), "+f"(c3)
                 : "r"(a0), "r"(a1), "r"(a2), "r"(a3), "r"(b0), "r"(b1));
}

// ---------------- prep: tf32-round x -----------------------------------------
__global__ void round_x_kernel(const float* __restrict__ x, float* __restrict__ xr) {
    size_t i = (size_t)blockIdx.x * blockDim.x + threadIdx.x;
    if (i >= (size_t)NNODES * NFEAT / 4) return;
    float4 v = ((const float4*)x)[i];
    v.x = cvt_tf32(v.x); v.y = cvt_tf32(v.y);
    v.z = cvt_tf32(v.z); v.w = cvt_tf32(v.w);
    ((float4*)xr)[i] = v;
}

// ---------------- prep: repack W1 [d][k][h] -> [k][d*64+h], tf32-rounded -----
__global__ void repack1_kernel(const float* __restrict__ W1, float* __restrict__ B1) {
    int i = blockIdx.x * blockDim.x + threadIdx.x;
    if (i >= NFEAT * HCAT) return;
    int k = i / HCAT, j = i - k * HCAT;
    int d = j >> 6, h = j & 63;
    B1[i] = cvt_tf32(W1[((size_t)d * NFEAT + k) * NHID + h]);
}

// ---------------- prep: repack W2 [d][k][c] -> [k][d*52+c] (c>=50 -> 0) ------
__global__ void repack2_kernel(const float* __restrict__ W2, float* __restrict__ B2) {
    int i = blockIdx.x * blockDim.x + threadIdx.x;
    if (i >= HCAT * NW2) return;
    int k = i / NW2, j = i - k * NW2;
    int d = j / NC2, c = j - d * NC2;
    B2[i] = (c < NCLASS) ? cvt_tf32(W2[((size_t)d * HCAT + k) * NCLASS + c]) : 0.f;
}

// ---------------- zero scatter accumulators ----------------------------------
__global__ void zero_kernel(float* __restrict__ h1cat, float* __restrict__ acc2) {
    size_t i  = (size_t)blockIdx.x * blockDim.x + threadIdx.x;
    const size_t n1 = (size_t)NNODES * HCAT / 4;
    const size_t n2 = (size_t)NNODES * NW2 / 4;
    float4 z = make_float4(0.f, 0.f, 0.f, 0.f);
    if (i < n1)            ((float4*)h1cat)[i]      = z;
    else if (i < n1 + n2)  ((float4*)acc2)[i - n1]  = z;
}

// ---------------- big tf32 tensor-core GEMM ----------------------------------
// C (NNODES x NTOT) = A (NNODES x K) * B (K x NTOT); inputs pre-rounded tf32.
// BM=128, BN=128, BK=32. 256 threads = 8 warps in 2(m) x 4(n), warp tile 64x32
// (mt=4, nt=4). Register-prefetch single-buffered SMEM.
template <int K, int NTOT>
__global__ void __launch_bounds__(256)
big_mma_kernel(const float* __restrict__ A, const float* __restrict__ B,
               float* __restrict__ C) {
    constexpr int BM = 128, BN = 128, BK = 32;
    constexpr int KTILES = (K + BK - 1) / BK;
    __shared__ float As[BM][36];    // pad 36: frag LDS banks 4g+tig (distinct)
    __shared__ float Bs[BK][132];   // pad 132: frag LDS banks 4tig+g (distinct)

    const int col0 = blockIdx.x * BN;
    const int n0   = blockIdx.y * BM;

    const int tid  = threadIdx.x;
    const int w    = tid >> 5;
    const int lane = tid & 31;
    const int g    = lane >> 2;
    const int tig  = lane & 3;
    const int wm   = (w & 1) * 64;        // 2 warp-rows of 64
    const int wn   = (w >> 1) * 32;       // 4 warp-cols of 32

    float acc[4][4][4];
    #pragma unroll
    for (int mt = 0; mt < 4; mt++)
        #pragma unroll
        for (int nt = 0; nt < 4; nt++)
            #pragma unroll
            for (int i = 0; i < 4; i++) acc[mt][nt][i] = 0.f;

    float aS[16], bS[16];

    // A tile: 128 x 32 = 4096 floats, 16/thread (4 x float4)
    auto loadA = [&](int k0) {
        #pragma unroll
        for (int j = 0; j < 4; j++) {
            int linear = tid + j * 256;
            int r  = linear >> 3;
            int c  = (linear & 7) * 4;
            int gr = n0 + r, gc = k0 + c;
            if (gr < NNODES && gc + 3 < K) {
                float4 v = *(const float4*)(A + (size_t)gr * K + gc);
                aS[j*4+0] = v.x; aS[j*4+1] = v.y; aS[j*4+2] = v.z; aS[j*4+3] = v.w;
            } else {
                #pragma unroll
                for (int i = 0; i < 4; i++)
                    aS[j*4+i] = (gr < NNODES && gc + i < K)
                                ? A[(size_t)gr * K + gc + i] : 0.f;
            }
        }
    };
    auto storeA = [&]() {
        #pragma unroll
        for (int j = 0; j < 4; j++) {
            int linear = tid + j * 256;
            int r = linear >> 3;
            int c = (linear & 7) * 4;
            *(float4*)&As[r][c] = make_float4(aS[j*4], aS[j*4+1], aS[j*4+2], aS[j*4+3]);
        }
    };
    // B tile: 32 x 128 = 4096 floats, 16/thread
    auto loadB = [&](int k0) {
        #pragma unroll
        for (int j = 0; j < 4; j++) {
            int linear = tid + j * 256;
            int r = linear >> 5;
            int c = (linear & 31) * 4;
            int gk = k0 + r, gc = col0 + c;
            if (gk < K && gc + 3 < NTOT) {
                float4 v = *(const float4*)(B + (size_t)gk * NTOT + gc);
                bS[j*4+0] = v.x; bS[j*4+1] = v.y; bS[j*4+2] = v.z; bS[j*4+3] = v.w;
            } else {
                #pragma unroll
                for (int i = 0; i < 4; i++)
                    bS[j*4+i] = (gk < K && gc + i < NTOT)
                                ? B[(size_t)gk * NTOT + gc + i] : 0.f;
            }
        }
    };
    auto storeB = [&]() {
        #pragma unroll
        for (int j = 0; j < 4; j++) {
            int linear = tid + j * 256;
            int r = linear >> 5;
            int c = (linear & 31) * 4;
            *(float4*)&Bs[r][c] = make_float4(bS[j*4], bS[j*4+1], bS[j*4+2], bS[j*4+3]);
        }
    };

    loadA(0); loadB(0);

    for (int t = 0; t < KTILES; t++) {
        storeA(); storeB();
        __syncthreads();
        if (t + 1 < KTILES) { loadA((t+1) * BK); loadB((t+1) * BK); }

        #pragma unroll
        for (int ks = 0; ks < 4; ks++) {
            int k = ks * 8;
            uint32_t a[4][4];
            #pragma unroll
            for (int mt = 0; mt < 4; mt++) {
                int m = wm + mt * 16;
                a[mt][0] = __float_as_uint(As[m + g    ][k + tig    ]);
                a[mt][1] = __float_as_uint(As[m + g + 8][k + tig    ]);
                a[mt][2] = __float_as_uint(As[m + g    ][k + tig + 4]);
                a[mt][3] = __float_as_uint(As[m + g + 8][k + tig + 4]);
            }
            uint32_t b[4][2];
            #pragma unroll
            for (int nt = 0; nt < 4; nt++) {
                int n = wn + nt * 8;
                b[nt][0] = __float_as_uint(Bs[k + tig    ][n + g]);
                b[nt][1] = __float_as_uint(Bs[k + tig + 4][n + g]);
            }
            #pragma unroll
            for (int mt = 0; mt < 4; mt++)
                #pragma unroll
                for (int nt = 0; nt < 4; nt++)
                    mma_tf32(acc[mt][nt][0], acc[mt][nt][1],
                             acc[mt][nt][2], acc[mt][nt][3],
                             a[mt][0], a[mt][1], a[mt][2], a[mt][3],
                             b[nt][0], b[nt][1]);
        }
        __syncthreads();
    }

    #pragma unroll
    for (int mt = 0; mt < 4; mt++) {
        int gr0 = n0 + wm + mt * 16 + g;
        #pragma unroll
        for (int nt = 0; nt < 4; nt++) {
            int gc = col0 + wn + nt * 8 + tig * 2;
            if (gc + 1 >= NTOT) continue;
            if (gr0 < NNODES)
                *(float2*)(C + (size_t)gr0 * NTOT + gc) =
                    make_float2(acc[mt][nt][0], acc[mt][nt][1]);
            if (gr0 + 8 < NNODES)
                *(float2*)(C + (size_t)(gr0 + 8) * NTOT + gc) =
                    make_float2(acc[mt][nt][2], acc[mt][nt][3]);
        }
    }
}

// ---------------- SpMM layer 1: 16 float4 lanes per edge ---------------------
// sup1 layout [n][d*64+h]; scatter into h1cat[row][d*64+...] (transpose free).
__global__ void spmm1_kernel(const int* __restrict__ rows,
                             const int* __restrict__ cols,
                             const float* __restrict__ vals, int E,
                             const float* __restrict__ sup1,
                             float* __restrict__ h1cat) {
    const int d = blockIdx.y;
    long t = (long)blockIdx.x * blockDim.x + threadIdx.x;
    int e = (int)(t >> 4);
    int lane = (int)(t & 15);
    if (e >= E) return;
    size_t eo = (size_t)d * E + e;
    int r = rows[eo];
    int c = cols[eo];
    float v = vals[eo];
    float4 s = *(const float4*)(sup1 + (size_t)c * HCAT + d * NHID + lane * 4);
    float4 p = make_float4(v * s.x, v * s.y, v * s.z, v * s.w);
    red_add_v4(h1cat + (size_t)r * HCAT + d * NHID + lane * 4, p);
}

// ---------------- bias + relu + tf32-round on h1cat --------------------------
__global__ void bias_relu_kernel(const float* __restrict__ b1,
                                 float* __restrict__ h1cat) {
    size_t i = (size_t)blockIdx.x * blockDim.x + threadIdx.x;
    if (i >= (size_t)NNODES * HCAT / 4) return;
    float4 h = ((float4*)h1cat)[i];
    int k = (int)(i % (HCAT / 4));
    float4 b = ((const float4*)b1)[k];
    h.x = cvt_tf32(fmaxf(h.x + b.x, 0.f));
    h.y = cvt_tf32(fmaxf(h.y + b.y, 0.f));
    h.z = cvt_tf32(fmaxf(h.z + b.z, 0.f));
    h.w = cvt_tf32(fmaxf(h.w + b.w, 0.f));
    ((float4*)h1cat)[i] = h;
}

// ---------------- SpMM layer 2: 13 float4 lanes per edge ---------------------
// sup2/acc2 layout [n][d*52+c].
__global__ void spmm2_kernel(const int* __restrict__ rows,
                             const int* __restrict__ cols,
                             const float* __restrict__ vals, int E,
                             const float* __restrict__ sup2,
                             float* __restrict__ acc2) {
    const int d = blockIdx.y;
    long t = (long)blockIdx.x * blockDim.x + threadIdx.x;
    int e = (int)(t / 13);
    int lane = (int)(t - 13L * e);
    if (e >= E) return;
    size_t eo = (size_t)d * E + e;
    int r = rows[eo];
    int c = cols[eo];
    float v = vals[eo];
    float4 s = *(const float4*)(sup2 + (size_t)c * NW2 + d * NC2 + lane * 4);
    float4 p = make_float4(v * s.x, v * s.y, v * s.z, v * s.w);
    red_add_v4(acc2 + (size_t)r * NW2 + d * NC2 + lane * 4, p);
}

// ---------------- bias + relu + max-pool over branches -----------------------
__global__ void final_kernel(const float* __restrict__ b2,
                             const float* __restrict__ acc2,
                             float* __restrict__ out) {
    int i = blockIdx.x * blockDim.x + threadIdx.x;
    if (i >= NNODES * NCLASS) return;
    int n = i / NCLASS, c = i % NCLASS;
    float m = 0.f;
    #pragma unroll
    for (int d = 0; d < DIMB; d++)
        m = fmaxf(m, acc2[(size_t)n * NW2 + d * NC2 + c] + b2[d * NCLASS + c]);
    out[i] = m;
}

// ---------------- launch ----------------------------------------------------
extern "C" void kernel_launch(void* const* d_in, const int* in_sizes, int n_in,
                              void* d_out, int out_size) {
    const float* x        = (const float*)d_in[0];
    const int*   adj_rows = (const int*)d_in[1];
    const int*   adj_cols = (const int*)d_in[2];
    const float* adj_vals = (const float*)d_in[3];
    const float* W1       = (const float*)d_in[4];
    const float* b1       = (const float*)d_in[5];
    const float* W2       = (const float*)d_in[6];
    const float* b2       = (const float*)d_in[7];
    float*       out      = (float*)d_out;

    const int E = in_sizes[1] / DIMB;

    float *p_xr, *p_w1, *p_w2, *p_sup1, *p_h1cat, *p_sup2, *p_acc2;
    cudaGetSymbolAddress((void**)&p_xr,    g_xr);
    cudaGetSymbolAddress((void**)&p_w1,    g_w1);
    cudaGetSymbolAddress((void**)&p_w2,    g_w2);
    cudaGetSymbolAddress((void**)&p_sup1,  g_sup1);
    cudaGetSymbolAddress((void**)&p_h1cat, g_h1cat);
    cudaGetSymbolAddress((void**)&p_sup2,  g_sup2);
    cudaGetSymbolAddress((void**)&p_acc2,  g_acc2);

    // prep: zero accumulators, round x, repack+round weights
    {
        size_t zn = ((size_t)NNODES * HCAT + (size_t)NNODES * NW2) / 4;
        zero_kernel<<<(unsigned)((zn + 255) / 256), 256>>>(p_h1cat, p_acc2);
    }
    round_x_kernel<<<(NNODES * NFEAT / 4 + 255) / 256, 256>>>(x, p_xr);
    repack1_kernel<<<(NFEAT * HCAT + 255) / 256, 256>>>(W1, p_w1);
    repack2_kernel<<<(HCAT * NW2 + 255) / 256, 256>>>(W2, p_w2);

    const int rowTiles = (NNODES + 127) / 128;

    // layer 1 GEMM: sup1[n][d*64+h] = xr * W1pk   (M=20000, N=1600, K=300)
    big_mma_kernel<NFEAT, HCAT>
        <<<dim3((HCAT + 127) / 128, rowTiles), 256>>>(p_xr, p_w1, p_sup1);

    // spmm layer 1 (scatter into permuted h1cat)
    {
        long threads = (long)E * 16;
        dim3 grid((unsigned)((threads + 255) / 256), DIMB);
        spmm1_kernel<<<grid, 256>>>(adj_rows, adj_cols, adj_vals, E, p_sup1, p_h1cat);
    }

    // bias + relu (+ tf32 rounding for next GEMM)
    {
        size_t n = (size_t)NNODES * HCAT / 4;
        bias_relu_kernel<<<(unsigned)((n + 255) / 256), 256>>>(b1, p_h1cat);
    }

    // layer 2 GEMM: sup2[n][d*52+c] = h1cat * W2pk (M=20000, N=1300, K=1600)
    big_mma_kernel<HCAT, NW2>
        <<<dim3((NW2 + 127) / 128, rowTiles), 256>>>(p_h1cat, p_w2, p_sup2);

    // spmm layer 2
    {
        long threads = (long)E * 13;
        dim3 grid((unsigned)((threads + 255) / 256), DIMB);
        spmm2_kernel<<<grid, 256>>>(adj_rows, adj_cols, adj_vals, E, p_sup2, p_acc2);
    }

    // bias + relu + max over branches
    final_kernel<<<(NNODES * NCLASS + 255) / 256, 256>>>(b2, p_acc2, out);
}

// round 4
// speedup vs baseline: 2.7656x; 1.7974x over previous
#include <cuda_runtime.h>
#include <cstdint>
#include <cstdio>

#define DIMB   25
#define NNODES 20000
#define NFEAT  300
#define NHID   64
#define NCLASS 50
#define NC2    52             // NCLASS padded to 52 (16B rows)
#define HCAT   (DIMB * NHID)  // 1600
#define NW2    (DIMB * NC2)   // 1300
#define EDGES  320000
#define BTOT   (DIMB * NNODES)         // 500000 bins
#define SCAN_BLKS ((BTOT + 1023) / 1024)  // 489

// ---------------- scratch (static device memory; no allocs allowed) ----------
__device__ float g_xr   [(size_t)NNODES * NFEAT];
__device__ float g_w1   [(size_t)NFEAT * HCAT];
__device__ float g_w2   [(size_t)HCAT * NW2];
__device__ float g_sup1 [(size_t)NNODES * HCAT];
__device__ float g_h1cat[(size_t)NNODES * HCAT];
__device__ float g_sup2 [(size_t)NNODES * NW2];
__device__ float g_acc2 [(size_t)NNODES * NW2];
// CSR build
__device__ int   g_cnt   [BTOT];
__device__ int   g_rowptr[BTOT + 1];
__device__ int   g_bsum  [1024];
__device__ int2  g_ecv   [(size_t)DIMB * EDGES];   // packed (col, val-bits)

// ---------------- helpers ----------------------------------------------------
__device__ __forceinline__ float cvt_tf32(float f) {
    uint32_t o;
    asm("cvt.rna.tf32.f32 %0, %1;" : "=r"(o) : "f"(f));
    return __uint_as_float(o);
}

__device__ __forceinline__ void mma_tf32(float& c0, float& c1, float& c2, float& c3,
                                         uint32_t a0, uint32_t a1, uint32_t a2, uint32_t a3,
                                         uint32_t b0, uint32_t b1) {
    asm volatile("mma.sync.aligned.m16n8k8.row.col.f32.tf32.tf32.f32 "
                 "{%0,%1,%2,%3}, {%4,%5,%6,%7}, {%8,%9}, {%0,%1,%2,%3};"
                 : "+f"(c0), "+f"(c1), "+f"(c2), "+f"(c3)
                 : "r"(a0), "r"(a1), "r"(a2), "r"(a3), "r"(b0), "r"(b1));
}

// ================= CSR construction ==========================================
__global__ void zero_cnt_kernel() {
    int i = blockIdx.x * blockDim.x + threadIdx.x;
    if (i < BTOT) g_cnt[i] = 0;
}

__global__ void hist_kernel(const int* __restrict__ rows, int E) {
    const int d = blockIdx.y;
    int e = blockIdx.x * blockDim.x + threadIdx.x;
    if (e >= E) return;
    atomicAdd(&g_cnt[d * NNODES + rows[(size_t)d * E + e]], 1);
}

__global__ void scan1_kernel() {
    __shared__ int sh[1024];
    int i = blockIdx.x * 1024 + threadIdx.x;
    int v = (i < BTOT) ? g_cnt[i] : 0;
    sh[threadIdx.x] = v;
    __syncthreads();
    #pragma unroll
    for (int off = 1; off < 1024; off <<= 1) {
        int t = (threadIdx.x >= off) ? sh[threadIdx.x - off] : 0;
        __syncthreads();
        sh[threadIdx.x] += t;
        __syncthreads();
    }
    if (i < BTOT) g_rowptr[i] = sh[threadIdx.x] - v;    // exclusive
    if (threadIdx.x == 1023) g_bsum[blockIdx.x] = sh[1023];
}

__global__ void scan2_kernel() {
    __shared__ int sh[1024];
    int v = (threadIdx.x < SCAN_BLKS) ? g_bsum[threadIdx.x] : 0;
    sh[threadIdx.x] = v;
    __syncthreads();
    #pragma unroll
    for (int off = 1; off < 1024; off <<= 1) {
        int t = (threadIdx.x >= off) ? sh[threadIdx.x - off] : 0;
        __syncthreads();
        sh[threadIdx.x] += t;
        __syncthreads();
    }
    if (threadIdx.x < SCAN_BLKS) g_bsum[threadIdx.x] = sh[threadIdx.x] - v;
}

__global__ void scan3_kernel(int total) {
    int i = blockIdx.x * 1024 + threadIdx.x;
    if (i < BTOT) {
        g_rowptr[i] += g_bsum[blockIdx.x];
        g_cnt[i] = 0;                       // reset counters for scatter
    }
    if (i == 0) g_rowptr[BTOT] = total;
}

__global__ void scatter_kernel(const int* __restrict__ rows,
                               const int* __restrict__ cols,
                               const float* __restrict__ vals, int E) {
    const int d = blockIdx.y;
    int e = blockIdx.x * blockDim.x + threadIdx.x;
    if (e >= E) return;
    size_t eo = (size_t)d * E + e;
    int bin = d * NNODES + rows[eo];
    int pos = g_rowptr[bin] + atomicAdd(&g_cnt[bin], 1);
    g_ecv[pos] = make_int2(cols[eo], __float_as_int(vals[eo]));
}

// ================= prep ======================================================
__global__ void round_x_kernel(const float* __restrict__ x, float* __restrict__ xr) {
    size_t i = (size_t)blockIdx.x * blockDim.x + threadIdx.x;
    if (i >= (size_t)NNODES * NFEAT / 4) return;
    float4 v = ((const float4*)x)[i];
    v.x = cvt_tf32(v.x); v.y = cvt_tf32(v.y);
    v.z = cvt_tf32(v.z); v.w = cvt_tf32(v.w);
    ((float4*)xr)[i] = v;
}

__global__ void repack1_kernel(const float* __restrict__ W1, float* __restrict__ B1) {
    int i = blockIdx.x * blockDim.x + threadIdx.x;
    if (i >= NFEAT * HCAT) return;
    int k = i / HCAT, j = i - k * HCAT;
    int d = j >> 6, h = j & 63;
    B1[i] = cvt_tf32(W1[((size_t)d * NFEAT + k) * NHID + h]);
}

__global__ void repack2_kernel(const float* __restrict__ W2, float* __restrict__ B2) {
    int i = blockIdx.x * blockDim.x + threadIdx.x;
    if (i >= HCAT * NW2) return;
    int k = i / NW2, j = i - k * NW2;
    int d = j / NC2, c = j - d * NC2;
    B2[i] = (c < NCLASS) ? cvt_tf32(W2[((size_t)d * HCAT + k) * NCLASS + c]) : 0.f;
}

// ================= big tf32 tensor-core GEMM =================================
// C (NNODES x NTOT) = A (NNODES x K) * B (K x NTOT); inputs pre-rounded tf32.
template <int K, int NTOT>
__global__ void __launch_bounds__(256)
big_mma_kernel(const float* __restrict__ A, const float* __restrict__ B,
               float* __restrict__ C) {
    constexpr int BM = 128, BN = 128, BK = 32;
    constexpr int KTILES = (K + BK - 1) / BK;
    __shared__ float As[BM][36];
    __shared__ float Bs[BK][132];

    const int col0 = blockIdx.x * BN;
    const int n0   = blockIdx.y * BM;

    const int tid  = threadIdx.x;
    const int w    = tid >> 5;
    const int lane = tid & 31;
    const int g    = lane >> 2;
    const int tig  = lane & 3;
    const int wm   = (w & 1) * 64;
    const int wn   = (w >> 1) * 32;

    float acc[4][4][4];
    #pragma unroll
    for (int mt = 0; mt < 4; mt++)
        #pragma unroll
        for (int nt = 0; nt < 4; nt++)
            #pragma unroll
            for (int i = 0; i < 4; i++) acc[mt][nt][i] = 0.f;

    float aS[16], bS[16];

    auto loadA = [&](int k0) {
        #pragma unroll
        for (int j = 0; j < 4; j++) {
            int linear = tid + j * 256;
            int r  = linear >> 3;
            int c  = (linear & 7) * 4;
            int gr = n0 + r, gc = k0 + c;
            if (gr < NNODES && gc + 3 < K) {
                float4 v = *(const float4*)(A + (size_t)gr * K + gc);
                aS[j*4+0] = v.x; aS[j*4+1] = v.y; aS[j*4+2] = v.z; aS[j*4+3] = v.w;
            } else {
                #pragma unroll
                for (int i = 0; i < 4; i++)
                    aS[j*4+i] = (gr < NNODES && gc + i < K)
                                ? A[(size_t)gr * K + gc + i] : 0.f;
            }
        }
    };
    auto storeA = [&]() {
        #pragma unroll
        for (int j = 0; j < 4; j++) {
            int linear = tid + j * 256;
            int r = linear >> 3;
            int c = (linear & 7) * 4;
            *(float4*)&As[r][c] = make_float4(aS[j*4], aS[j*4+1], aS[j*4+2], aS[j*4+3]);
        }
    };
    auto loadB = [&](int k0) {
        #pragma unroll
        for (int j = 0; j < 4; j++) {
            int linear = tid + j * 256;
            int r = linear >> 5;
            int c = (linear & 31) * 4;
            int gk = k0 + r, gc = col0 + c;
            if (gk < K && gc + 3 < NTOT) {
                float4 v = *(const float4*)(B + (size_t)gk * NTOT + gc);
                bS[j*4+0] = v.x; bS[j*4+1] = v.y; bS[j*4+2] = v.z; bS[j*4+3] = v.w;
            } else {
                #pragma unroll
                for (int i = 0; i < 4; i++)
                    bS[j*4+i] = (gk < K && gc + i < NTOT)
                                ? B[(size_t)gk * NTOT + gc + i] : 0.f;
            }
        }
    };
    auto storeB = [&]() {
        #pragma unroll
        for (int j = 0; j < 4; j++) {
            int linear = tid + j * 256;
            int r = linear >> 5;
            int c = (linear & 31) * 4;
            *(float4*)&Bs[r][c] = make_float4(bS[j*4], bS[j*4+1], bS[j*4+2], bS[j*4+3]);
        }
    };

    loadA(0); loadB(0);

    for (int t = 0; t < KTILES; t++) {
        storeA(); storeB();
        __syncthreads();
        if (t + 1 < KTILES) { loadA((t+1) * BK); loadB((t+1) * BK); }

        #pragma unroll
        for (int ks = 0; ks < 4; ks++) {
            int k = ks * 8;
            uint32_t a[4][4];
            #pragma unroll
            for (int mt = 0; mt < 4; mt++) {
                int m = wm + mt * 16;
                a[mt][0] = __float_as_uint(As[m + g    ][k + tig    ]);
                a[mt][1] = __float_as_uint(As[m + g + 8][k + tig    ]);
                a[mt][2] = __float_as_uint(As[m + g    ][k + tig + 4]);
                a[mt][3] = __float_as_uint(As[m + g + 8][k + tig + 4]);
            }
            uint32_t b[4][2];
            #pragma unroll
            for (int nt = 0; nt < 4; nt++) {
                int n = wn + nt * 8;
                b[nt][0] = __float_as_uint(Bs[k + tig    ][n + g]);
                b[nt][1] = __float_as_uint(Bs[k + tig + 4][n + g]);
            }
            #pragma unroll
            for (int mt = 0; mt < 4; mt++)
                #pragma unroll
                for (int nt = 0; nt < 4; nt++)
                    mma_tf32(acc[mt][nt][0], acc[mt][nt][1],
                             acc[mt][nt][2], acc[mt][nt][3],
                             a[mt][0], a[mt][1], a[mt][2], a[mt][3],
                             b[nt][0], b[nt][1]);
        }
        __syncthreads();
    }

    #pragma unroll
    for (int mt = 0; mt < 4; mt++) {
        int gr0 = n0 + wm + mt * 16 + g;
        #pragma unroll
        for (int nt = 0; nt < 4; nt++) {
            int gc = col0 + wn + nt * 8 + tig * 2;
            if (gc + 1 >= NTOT) continue;
            if (gr0 < NNODES)
                *(float2*)(C + (size_t)gr0 * NTOT + gc) =
                    make_float2(acc[mt][nt][0], acc[mt][nt][1]);
            if (gr0 + 8 < NNODES)
                *(float2*)(C + (size_t)(gr0 + 8) * NTOT + gc) =
                    make_float2(acc[mt][nt][2], acc[mt][nt][3]);
        }
    }
}

// ================= CSR SpMM layer 1 (+ fused bias/relu/tf32) =================
// One warp per (d, row): gather-accumulate in registers, write row once.
// Payload 64 floats = float2 per lane.
__global__ void __launch_bounds__(256)
spmm1_csr_kernel(const float* __restrict__ sup1, const float* __restrict__ b1,
                 float* __restrict__ h1cat) {
    const int d   = blockIdx.y;
    const int wid = threadIdx.x >> 5;
    const int lane = threadIdx.x & 31;
    const int row = blockIdx.x * 8 + wid;
    if (row >= NNODES) return;

    const int bin   = d * NNODES + row;
    int j   = g_rowptr[bin];
    const int end = g_rowptr[bin + 1];
    const int off = d * NHID + lane * 2;

    float2 acc = make_float2(0.f, 0.f);
    for (; j + 1 < end; j += 2) {
        int2 cv0 = g_ecv[j];
        int2 cv1 = g_ecv[j + 1];
        float v0 = __int_as_float(cv0.y);
        float v1 = __int_as_float(cv1.y);
        float2 s0 = *(const float2*)(sup1 + (size_t)cv0.x * HCAT + off);
        float2 s1 = *(const float2*)(sup1 + (size_t)cv1.x * HCAT + off);
        acc.x += v0 * s0.x + v1 * s1.x;
        acc.y += v0 * s0.y + v1 * s1.y;
    }
    if (j < end) {
        int2 cv = g_ecv[j];
        float v = __int_as_float(cv.y);
        float2 s = *(const float2*)(sup1 + (size_t)cv.x * HCAT + off);
        acc.x += v * s.x;
        acc.y += v * s.y;
    }

    float2 b = *(const float2*)(b1 + off);
    acc.x = cvt_tf32(fmaxf(acc.x + b.x, 0.f));
    acc.y = cvt_tf32(fmaxf(acc.y + b.y, 0.f));
    *(float2*)(h1cat + (size_t)row * HCAT + off) = acc;
}

// ================= CSR SpMM layer 2 ==========================================
// Payload 52 floats = float2 on lanes 0..25.
__global__ void __launch_bounds__(256)
spmm2_csr_kernel(const float* __restrict__ sup2, float* __restrict__ acc2) {
    const int d   = blockIdx.y;
    const int wid = threadIdx.x >> 5;
    const int lane = threadIdx.x & 31;
    const int row = blockIdx.x * 8 + wid;
    if (row >= NNODES) return;
    const bool act = lane < 26;

    const int bin = d * NNODES + row;
    int j   = g_rowptr[bin];
    const int end = g_rowptr[bin + 1];
    const int off = d * NC2 + lane * 2;

    float2 acc = make_float2(0.f, 0.f);
    for (; j + 1 < end; j += 2) {
        int2 cv0 = g_ecv[j];
        int2 cv1 = g_ecv[j + 1];
        if (act) {
            float v0 = __int_as_float(cv0.y);
            float v1 = __int_as_float(cv1.y);
            float2 s0 = *(const float2*)(sup2 + (size_t)cv0.x * NW2 + off);
            float2 s1 = *(const float2*)(sup2 + (size_t)cv1.x * NW2 + off);
            acc.x += v0 * s0.x + v1 * s1.x;
            acc.y += v0 * s0.y + v1 * s1.y;
        }
    }
    if (j < end && act) {
        int2 cv = g_ecv[j];
        float v = __int_as_float(cv.y);
        float2 s = *(const float2*)(sup2 + (size_t)cv.x * NW2 + off);
        acc.x += v * s.x;
        acc.y += v * s.y;
    }
    if (act)
        *(float2*)(acc2 + (size_t)row * NW2 + off) = acc;
}

// ================= bias + relu + max-pool over branches ======================
__global__ void final_kernel(const float* __restrict__ b2,
                             const float* __restrict__ acc2,
                             float* __restrict__ out) {
    int i = blockIdx.x * blockDim.x + threadIdx.x;
    if (i >= NNODES * NCLASS) return;
    int n = i / NCLASS, c = i % NCLASS;
    float m = 0.f;
    #pragma unroll
    for (int d = 0; d < DIMB; d++)
        m = fmaxf(m, acc2[(size_t)n * NW2 + d * NC2 + c] + b2[d * NCLASS + c]);
    out[i] = m;
}

// ================= launch ====================================================
extern "C" void kernel_launch(void* const* d_in, const int* in_sizes, int n_in,
                              void* d_out, int out_size) {
    const float* x        = (const float*)d_in[0];
    const int*   adj_rows = (const int*)d_in[1];
    const int*   adj_cols = (const int*)d_in[2];
    const float* adj_vals = (const float*)d_in[3];
    const float* W1       = (const float*)d_in[4];
    const float* b1       = (const float*)d_in[5];
    const float* W2       = (const float*)d_in[6];
    const float* b2       = (const float*)d_in[7];
    float*       out      = (float*)d_out;

    const int E = in_sizes[1] / DIMB;

    float *p_xr, *p_w1, *p_w2, *p_sup1, *p_h1cat, *p_sup2, *p_acc2;
    cudaGetSymbolAddress((void**)&p_xr,    g_xr);
    cudaGetSymbolAddress((void**)&p_w1,    g_w1);
    cudaGetSymbolAddress((void**)&p_w2,    g_w2);
    cudaGetSymbolAddress((void**)&p_sup1,  g_sup1);
    cudaGetSymbolAddress((void**)&p_h1cat, g_h1cat);
    cudaGetSymbolAddress((void**)&p_sup2,  g_sup2);
    cudaGetSymbolAddress((void**)&p_acc2,  g_acc2);

    const dim3 egrid((E + 255) / 256, DIMB);

    // --- CSR build -----------------------------------------------------------
    zero_cnt_kernel<<<(BTOT + 255) / 256, 256>>>();
    hist_kernel<<<egrid, 256>>>(adj_rows, E);
    scan1_kernel<<<SCAN_BLKS, 1024>>>();
    scan2_kernel<<<1, 1024>>>();
    scan3_kernel<<<SCAN_BLKS, 1024>>>(DIMB * E);
    scatter_kernel<<<egrid, 256>>>(adj_rows, adj_cols, adj_vals, E);

    // --- prep: round x, repack weights --------------------------------------
    round_x_kernel<<<(NNODES * NFEAT / 4 + 255) / 256, 256>>>(x, p_xr);
    repack1_kernel<<<(NFEAT * HCAT + 255) / 256, 256>>>(W1, p_w1);
    repack2_kernel<<<(HCAT * NW2 + 255) / 256, 256>>>(W2, p_w2);

    const int rowTiles = (NNODES + 127) / 128;

    // --- layer 1: GEMM + CSR spmm (fused bias/relu) --------------------------
    big_mma_kernel<NFEAT, HCAT>
        <<<dim3((HCAT + 127) / 128, rowTiles), 256>>>(p_xr, p_w1, p_sup1);
    spmm1_csr_kernel<<<dim3(NNODES / 8, DIMB), 256>>>(p_sup1, b1, p_h1cat);

    // --- layer 2: GEMM + CSR spmm -------------------------------------------
    big_mma_kernel<HCAT, NW2>
        <<<dim3((NW2 + 127) / 128, rowTiles), 256>>>(p_h1cat, p_w2, p_sup2);
    spmm2_csr_kernel<<<dim3(NNODES / 8, DIMB), 256>>>(p_sup2, p_acc2);

    // --- epilogue ------------------------------------------------------------
    final_kernel<<<(NNODES * NCLASS + 255) / 256, 256>>>(b2, p_acc2, out);
}

// round 6
// speedup vs baseline: 3.5847x; 1.2962x over previous
#include <cuda_runtime.h>
#include <cuda_fp16.h>
#include <cstdint>
#include <cstdio>

#define DIMB   25
#define NNODES 20000
#define NFEAT  300
#define KPAD1  320            // NFEAT padded to multiple of 32
#define NHID   64
#define NCLASS 50
#define NC2    52             // NCLASS padded to 52
#define HCAT   (DIMB * NHID)  // 1600 (K of layer-2 GEMM, %32==0)
#define NW2    (DIMB * NC2)   // 1300
#define EDGES  320000
#define BTOT   (DIMB * NNODES)
#define SCAN_BLKS ((BTOT + 1023) / 1024)

// ---------------- scratch (static device memory; no allocs allowed) ----------
__device__ __half g_xh  [(size_t)NNODES * KPAD1];   // fp16 x, padded
__device__ __half g_w1h [(size_t)HCAT * KPAD1];     // W1 repacked n-major fp16
__device__ __half g_w2h [(size_t)NW2 * HCAT];       // W2 repacked n-major fp16
__device__ float  g_sup1 [(size_t)NNODES * HCAT];
__device__ __half g_h1h [(size_t)NNODES * HCAT];    // fp16 h1cat
__device__ float  g_sup2 [(size_t)NNODES * NW2];
__device__ float  g_acc2 [(size_t)NNODES * NW2];
// CSR build
__device__ int   g_cnt   [BTOT];
__device__ int   g_rowptr[BTOT + 1];
__device__ int   g_bsum  [1024];
__device__ int2  g_ecv   [(size_t)DIMB * EDGES];

// ---------------- helpers ----------------------------------------------------
__device__ __forceinline__ void mma_f16(float& c0, float& c1, float& c2, float& c3,
                                        uint32_t a0, uint32_t a1, uint32_t a2, uint32_t a3,
                                        uint32_t b0, uint32_t b1) {
    asm volatile("mma.sync.aligned.m16n8k16.row.col.f32.f16.f16.f32 "
                 "{%0,%1,%2,%3}, {%4,%5,%6,%7}, {%8,%9}, {%0,%1,%2,%3};"
                 : "+f"(c0), "+f"(c1), "+f"(c2), "+f"(c3)
                 : "r"(a0), "r"(a1), "r"(a2), "r"(a3), "r"(b0), "r"(b1));
}

// ================= CSR construction ==========================================
__global__ void zero_cnt_kernel() {
    int i = blockIdx.x * blockDim.x + threadIdx.x;
    if (i < BTOT) g_cnt[i] = 0;
}

__global__ void hist_kernel(const int* __restrict__ rows, int E) {
    const int d = blockIdx.y;
    int e = blockIdx.x * blockDim.x + threadIdx.x;
    if (e >= E) return;
    atomicAdd(&g_cnt[d * NNODES + rows[(size_t)d * E + e]], 1);
}

__global__ void scan1_kernel() {
    __shared__ int sh[1024];
    int i = blockIdx.x * 1024 + threadIdx.x;
    int v = (i < BTOT) ? g_cnt[i] : 0;
    sh[threadIdx.x] = v;
    __syncthreads();
    #pragma unroll
    for (int off = 1; off < 1024; off <<= 1) {
        int t = (threadIdx.x >= off) ? sh[threadIdx.x - off] : 0;
        __syncthreads();
        sh[threadIdx.x] += t;
        __syncthreads();
    }
    if (i < BTOT) g_rowptr[i] = sh[threadIdx.x] - v;
    if (threadIdx.x == 1023) g_bsum[blockIdx.x] = sh[1023];
}

__global__ void scan2_kernel() {
    __shared__ int sh[1024];
    int v = (threadIdx.x < SCAN_BLKS) ? g_bsum[threadIdx.x] : 0;
    sh[threadIdx.x] = v;
    __syncthreads();
    #pragma unroll
    for (int off = 1; off < 1024; off <<= 1) {
        int t = (threadIdx.x >= off) ? sh[threadIdx.x - off] : 0;
        __syncthreads();
        sh[threadIdx.x] += t;
        __syncthreads();
    }
    if (threadIdx.x < SCAN_BLKS) g_bsum[threadIdx.x] = sh[threadIdx.x] - v;
}

__global__ void scan3_kernel(int total) {
    int i = blockIdx.x * 1024 + threadIdx.x;
    if (i < BTOT) {
        g_rowptr[i] += g_bsum[blockIdx.x];
        g_cnt[i] = 0;
    }
    if (i == 0) g_rowptr[BTOT] = total;
}

__global__ void scatter_kernel(const int* __restrict__ rows,
                               const int* __restrict__ cols,
                               const float* __restrict__ vals, int E) {
    const int d = blockIdx.y;
    int e = blockIdx.x * blockDim.x + threadIdx.x;
    if (e >= E) return;
    size_t eo = (size_t)d * E + e;
    int bin = d * NNODES + rows[eo];
    int pos = g_rowptr[bin] + atomicAdd(&g_cnt[bin], 1);
    g_ecv[pos] = make_int2(cols[eo], __float_as_int(vals[eo]));
}

// ================= prep ======================================================
// x [n][300] fp32 -> xh [n][320] fp16, zero-padded
__global__ void cvt_x_kernel(const float* __restrict__ x, __half* __restrict__ xh) {
    size_t i = (size_t)blockIdx.x * blockDim.x + threadIdx.x;
    if (i >= (size_t)NNODES * KPAD1 / 4) return;
    int n   = (int)(i / (KPAD1 / 4));
    int col = ((int)(i % (KPAD1 / 4))) * 4;
    __half2 lo = __floats2half2_rn(0.f, 0.f), hi = lo;
    if (col < NFEAT) {
        float4 v = *(const float4*)(x + (size_t)n * NFEAT + col);
        lo = __floats2half2_rn(v.x, v.y);
        hi = __floats2half2_rn(v.z, v.w);
    }
    *(uint2*)(xh + i * 4) = make_uint2(*(uint32_t*)&lo, *(uint32_t*)&hi);
}

// W1 [d][k][h] -> w1h [n=d*64+h][k pad 320] fp16
__global__ void repack1_kernel(const float* __restrict__ W1, __half* __restrict__ B1) {
    int i = blockIdx.x * blockDim.x + threadIdx.x;
    if (i >= HCAT * KPAD1) return;
    int n = i / KPAD1, k = i - n * KPAD1;
    int d = n >> 6, h = n & 63;
    B1[i] = (k < NFEAT) ? __float2half_rn(W1[((size_t)d * NFEAT + k) * NHID + h])
                        : __float2half_rn(0.f);
}

// W2 [d][k][c] -> w2h [n=d*52+c][k] fp16
__global__ void repack2_kernel(const float* __restrict__ W2, __half* __restrict__ B2) {
    int i = blockIdx.x * blockDim.x + threadIdx.x;
    if (i >= NW2 * HCAT) return;
    int n = i / HCAT, k = i - n * HCAT;
    int d = n / NC2, c = n - d * NC2;
    B2[i] = (c < NCLASS) ? __float2half_rn(W2[((size_t)d * HCAT + k) * NCLASS + c])
                         : __float2half_rn(0.f);
}

// ================= fp16 tensor-core GEMM =====================================
// C (NNODES x NTOT) = A (NNODES x KPAD) * Bt (NTOT x KPAD)^T, fp32 accumulate.
// BM=128, BN=128, BK=32. 8 warps 2(m) x 4(n), warp tile 64x32.
// mma.m16n8k16; SMEM stride 40 halves -> conflict-free fragment LDS.
template <int KPAD, int NTOT>
__global__ void __launch_bounds__(256)
h_mma_kernel(const __half* __restrict__ A, const __half* __restrict__ Bt,
             float* __restrict__ C) {
    constexpr int BM = 128, BK = 32;
    constexpr int KT = KPAD / BK;
    __shared__ __half As[BM][40];
    __shared__ __half Bs[BM][40];   // B rows are output cols (n-major)

    const int col0 = blockIdx.x * 128;
    const int m0   = blockIdx.y * BM;

    const int tid  = threadIdx.x;
    const int w    = tid >> 5;
    const int lane = tid & 31;
    const int g    = lane >> 2;
    const int tig  = lane & 3;
    const int wm   = (w & 1) * 64;
    const int wn   = (w >> 1) * 32;

    float acc[4][4][4];
    #pragma unroll
    for (int mt = 0; mt < 4; mt++)
        #pragma unroll
        for (int nt = 0; nt < 4; nt++)
            #pragma unroll
            for (int i = 0; i < 4; i++) acc[mt][nt][i] = 0.f;

    uint4 aS[2], bS[2];
    const uint4 z4 = make_uint4(0, 0, 0, 0);

    // stage: 128 rows x 32 halves (64B/row) each for A and B; 2 x uint4/thread
    auto loadT = [&](int k0) {
        #pragma unroll
        for (int j = 0; j < 2; j++) {
            int id = tid + j * 256;           // 0..511
            int r  = id >> 2;                 // 0..127
            int c8 = (id & 3) * 8;            // 0,8,16,24
            int gr = m0 + r;
            aS[j] = (gr < NNODES) ? *(const uint4*)(A + (size_t)gr * KPAD + k0 + c8) : z4;
            int gn = col0 + r;
            bS[j] = (gn < NTOT) ? *(const uint4*)(Bt + (size_t)gn * KPAD + k0 + c8) : z4;
        }
    };
    auto storeT = [&]() {
        #pragma unroll
        for (int j = 0; j < 2; j++) {
            int id = tid + j * 256;
            int r  = id >> 2;
            int c8 = (id & 3) * 8;
            *(uint4*)&As[r][c8] = aS[j];
            *(uint4*)&Bs[r][c8] = bS[j];
        }
    };

    loadT(0);

    for (int t = 0; t < KT; t++) {
        storeT();
        __syncthreads();
        if (t + 1 < KT) loadT((t + 1) * BK);

        #pragma unroll
        for (int ks = 0; ks < 2; ks++) {
            const int k = ks * 16;
            uint32_t a[4][4];
            #pragma unroll
            for (int mt = 0; mt < 4; mt++) {
                int m = wm + mt * 16;
                a[mt][0] = *(const uint32_t*)&As[m + g    ][k + 2 * tig    ];
                a[mt][1] = *(const uint32_t*)&As[m + g + 8][k + 2 * tig    ];
                a[mt][2] = *(const uint32_t*)&As[m + g    ][k + 2 * tig + 8];
                a[mt][3] = *(const uint32_t*)&As[m + g + 8][k + 2 * tig + 8];
            }
            uint32_t b[4][2];
            #pragma unroll
            for (int nt = 0; nt < 4; nt++) {
                int n = wn + nt * 8;
                b[nt][0] = *(const uint32_t*)&Bs[n + g][k + 2 * tig    ];
                b[nt][1] = *(const uint32_t*)&Bs[n + g][k + 2 * tig + 8];
            }
            #pragma unroll
            for (int mt = 0; mt < 4; mt++)
                #pragma unroll
                for (int nt = 0; nt < 4; nt++)
                    mma_f16(acc[mt][nt][0], acc[mt][nt][1],
                            acc[mt][nt][2], acc[mt][nt][3],
                            a[mt][0], a[mt][1], a[mt][2], a[mt][3],
                            b[nt][0], b[nt][1]);
        }
        __syncthreads();
    }

    #pragma unroll
    for (int mt = 0; mt < 4; mt++) {
        int gr0 = m0 + wm + mt * 16 + g;
        #pragma unroll
        for (int nt = 0; nt < 4; nt++) {
            int gc = col0 + wn + nt * 8 + tig * 2;
            if (gc + 1 >= NTOT) continue;
            if (gr0 < NNODES)
                *(float2*)(C + (size_t)gr0 * NTOT + gc) =
                    make_float2(acc[mt][nt][0], acc[mt][nt][1]);
            if (gr0 + 8 < NNODES)
                *(float2*)(C + (size_t)(gr0 + 8) * NTOT + gc) =
                    make_float2(acc[mt][nt][2], acc[mt][nt][3]);
        }
    }
}

// ================= CSR SpMM layer 1 (+ fused bias/relu -> fp16) ==============
__global__ void __launch_bounds__(256)
spmm1_csr_kernel(const float* __restrict__ sup1, const float* __restrict__ b1,
                 __half* __restrict__ h1h) {
    const int d    = blockIdx.y;
    const int wid  = threadIdx.x >> 5;
    const int lane = threadIdx.x & 31;
    const int row  = blockIdx.x * 8 + wid;
    if (row >= NNODES) return;

    const int bin = d * NNODES + row;
    int j         = g_rowptr[bin];
    const int end = g_rowptr[bin + 1];
    const int off = d * NHID + lane * 2;

    float2 acc = make_float2(0.f, 0.f);
    for (; j + 1 < end; j += 2) {
        int2 cv0 = g_ecv[j];
        int2 cv1 = g_ecv[j + 1];
        float v0 = __int_as_float(cv0.y);
        float v1 = __int_as_float(cv1.y);
        float2 s0 = *(const float2*)(sup1 + (size_t)cv0.x * HCAT + off);
        float2 s1 = *(const float2*)(sup1 + (size_t)cv1.x * HCAT + off);
        acc.x += v0 * s0.x + v1 * s1.x;
        acc.y += v0 * s0.y + v1 * s1.y;
    }
    if (j < end) {
        int2 cv = g_ecv[j];
        float v = __int_as_float(cv.y);
        float2 s = *(const float2*)(sup1 + (size_t)cv.x * HCAT + off);
        acc.x += v * s.x;
        acc.y += v * s.y;
    }

    float2 b = *(const float2*)(b1 + off);
    acc.x = fmaxf(acc.x + b.x, 0.f);
    acc.y = fmaxf(acc.y + b.y, 0.f);
    *(__half2*)(h1h + (size_t)row * HCAT + off) = __floats2half2_rn(acc.x, acc.y);
}

// ================= CSR SpMM layer 2 ==========================================
__global__ void __launch_bounds__(256)
spmm2_csr_kernel(const float* __restrict__ sup2, float* __restrict__ acc2) {
    const int d    = blockIdx.y;
    const int wid  = threadIdx.x >> 5;
    const int lane = threadIdx.x & 31;
    const int row  = blockIdx.x * 8 + wid;
    if (row >= NNODES) return;
    const bool act = lane < 26;

    const int bin = d * NNODES + row;
    int j         = g_rowptr[bin];
    const int end = g_rowptr[bin + 1];
    const int off = d * NC2 + lane * 2;

    float2 acc = make_float2(0.f, 0.f);
    for (; j + 1 < end; j += 2) {
        int2 cv0 = g_ecv[j];
        int2 cv1 = g_ecv[j + 1];
        if (act) {
            float v0 = __int_as_float(cv0.y);
            float v1 = __int_as_float(cv1.y);
            float2 s0 = *(const float2*)(sup2 + (size_t)cv0.x * NW2 + off);
            float2 s1 = *(const float2*)(sup2 + (size_t)cv1.x * NW2 + off);
            acc.x += v0 * s0.x + v1 * s1.x;
            acc.y += v0 * s0.y + v1 * s1.y;
        }
    }
    if (j < end && act) {
        int2 cv = g_ecv[j];
        float v = __int_as_float(cv.y);
        float2 s = *(const float2*)(sup2 + (size_t)cv.x * NW2 + off);
        acc.x += v * s.x;
        acc.y += v * s.y;
    }
    if (act)
        *(float2*)(acc2 + (size_t)row * NW2 + off) = acc;
}

// ================= bias + relu + max-pool over branches ======================
__global__ void final_kernel(const float* __restrict__ b2,
                             const float* __restrict__ acc2,
                             float* __restrict__ out) {
    int i = blockIdx.x * blockDim.x + threadIdx.x;
    if (i >= NNODES * NCLASS) return;
    int n = i / NCLASS, c = i % NCLASS;
    float m = 0.f;
    #pragma unroll
    for (int d = 0; d < DIMB; d++)
        m = fmaxf(m, acc2[(size_t)n * NW2 + d * NC2 + c] + b2[d * NCLASS + c]);
    out[i] = m;
}

// ================= launch ====================================================
extern "C" void kernel_launch(void* const* d_in, const int* in_sizes, int n_in,
                              void* d_out, int out_size) {
    const float* x        = (const float*)d_in[0];
    const int*   adj_rows = (const int*)d_in[1];
    const int*   adj_cols = (const int*)d_in[2];
    const float* adj_vals = (const float*)d_in[3];
    const float* W1       = (const float*)d_in[4];
    const float* b1       = (const float*)d_in[5];
    const float* W2       = (const float*)d_in[6];
    const float* b2       = (const float*)d_in[7];
    float*       out      = (float*)d_out;

    const int E = in_sizes[1] / DIMB;

    __half *p_xh, *p_w1h, *p_w2h, *p_h1h;
    float *p_sup1, *p_sup2, *p_acc2;
    cudaGetSymbolAddress((void**)&p_xh,    g_xh);
    cudaGetSymbolAddress((void**)&p_w1h,   g_w1h);
    cudaGetSymbolAddress((void**)&p_w2h,   g_w2h);
    cudaGetSymbolAddress((void**)&p_sup1,  g_sup1);
    cudaGetSymbolAddress((void**)&p_h1h,   g_h1h);
    cudaGetSymbolAddress((void**)&p_sup2,  g_sup2);
    cudaGetSymbolAddress((void**)&p_acc2,  g_acc2);

    const dim3 egrid((E + 255) / 256, DIMB);

    // --- CSR build -----------------------------------------------------------
    zero_cnt_kernel<<<(BTOT + 255) / 256, 256>>>();
    hist_kernel<<<egrid, 256>>>(adj_rows, E);
    scan1_kernel<<<SCAN_BLKS, 1024>>>();
    scan2_kernel<<<1, 1024>>>();
    scan3_kernel<<<SCAN_BLKS, 1024>>>(DIMB * E);
    scatter_kernel<<<egrid, 256>>>(adj_rows, adj_cols, adj_vals, E);

    // --- prep: convert x, repack weights to fp16 -----------------------------
    cvt_x_kernel<<<(NNODES * KPAD1 / 4 + 255) / 256, 256>>>(x, p_xh);
    repack1_kernel<<<(HCAT * KPAD1 + 255) / 256, 256>>>(W1, p_w1h);
    repack2_kernel<<<(NW2 * HCAT + 255) / 256, 256>>>(W2, p_w2h);

    const int mTiles = (NNODES + 127) / 128;

    // --- layer 1: fp16 GEMM + CSR spmm (fused bias/relu -> fp16) -------------
    h_mma_kernel<KPAD1, HCAT>
        <<<dim3((HCAT + 127) / 128, mTiles), 256>>>(p_xh, p_w1h, p_sup1);
    spmm1_csr_kernel<<<dim3(NNODES / 8, DIMB), 256>>>(p_sup1, b1, p_h1h);

    // --- layer 2: fp16 GEMM + CSR spmm ---------------------------------------
    h_mma_kernel<HCAT, NW2>
        <<<dim3((NW2 + 127) / 128, mTiles), 256>>>(p_h1h, p_w2h, p_sup2);
    spmm2_csr_kernel<<<dim3(NNODES / 8, DIMB), 256>>>(p_sup2, p_acc2);

    // --- epilogue ------------------------------------------------------------
    final_kernel<<<(NNODES * NCLASS + 255) / 256, 256>>>(b2, p_acc2, out);
}